// round 10
// baseline (speedup 1.0000x reference)
#include <cuda_runtime.h>
#include <cuda_bf16.h>
#include <cstdint>
#include <math.h>

// Problem constants (match reference)
#define K_NUM    131072
#define IN_NUM_  50000
#define OUT_NUM_ 50000
#define FEAT_    128
#define NPTS     16     // 4 neighbor combos + 12 sampled
#define ADD_     12
#define EPS_     1e-7f

// Cephes-classic f32 exp exactly as XLA:CPU / old-Eigen pexp emit it on an
// FMA-capable target (aarch64 NEON: pmadd == vfma). Op-for-op replication:
//   fx  = floor(fma(x, log2e, 0.5))
//   xr  = x - fx*C1 - fx*C2            (two muls + two subs, NOT fused)
//   y   = Horner(p0..p5 over xr, FMA)  ; y = fma(y, xr*xr, xr) + 1
//   out = y * 2^n  (exponent-bit construction)
// Inputs here satisfy |x| < 7, so the clamp and overflow paths never engage.
__device__ __forceinline__ float cephes_expf_fma(float x) {
    const float LOG2EF = 1.44269504088896341f;
    const float C1     = 0.693359375f;
    const float C2     = -2.12194440e-4f;

    float fx = __fmaf_rn(x, LOG2EF, 0.5f);
    fx = floorf(fx);

    const float tmp = __fmul_rn(fx, C1);
    const float z   = __fmul_rn(fx, C2);
    float xr = __fsub_rn(x, tmp);
    xr = __fsub_rn(xr, z);

    const float zz = __fmul_rn(xr, xr);

    float y =             1.9875691500e-4f;
    y = __fmaf_rn(y, xr,  1.3981999507e-3f);
    y = __fmaf_rn(y, xr,  8.3334519073e-3f);
    y = __fmaf_rn(y, xr,  4.1665795894e-2f);
    y = __fmaf_rn(y, xr,  1.6666665459e-1f);
    y = __fmaf_rn(y, xr,  5.0000001201e-1f);
    y = __fmaf_rn(y, zz,  xr);
    y = __fadd_rn(y, 1.0f);

    const int n = (int)fx;                       // fx integral, |n| <= 10
    const float p2n = __int_as_float((n + 127) << 23);
    return __fmul_rn(y, p2n);
}

// XLA logistic_expander: logistic(x) = 1 / (1 + exp(-x)); IEEE add + div.
__device__ __forceinline__ float sigmoid_ref(float v) {
    const float e = cephes_expf_fma(-v);
    return __fdiv_rn(1.0f, __fadd_rn(1.0f, e));
}

// softplus(x) = max(x,0) + log1p(exp(-|x|)); smooth — sigma enters only via
// props which are insensitive at the 1e-3 level. Double precision is ample.
__device__ __forceinline__ float softplus_acc(float v) {
    double d = (double)v;
    return (float)(fmax(d, 0.0) + log1p(exp(-fabs(d))));
}

__global__ void __launch_bounds__(512)
hyperlayer_scatter_kernel(const float* __restrict__ params,     // (K, 4)
                          const float* __restrict__ x,          // (IN_NUM, 128)
                          const int*   __restrict__ sampled,    // (K, 12, 2) : (i_out, j_in)
                          float*       __restrict__ out)        // (OUT_NUM, 128)
{
    __shared__ float s_w[NPTS];
    __shared__ int   s_i[NPTS];
    __shared__ int   s_j[NPTS];
    __shared__ float s_prop[NPTS];
    __shared__ float s_m0, s_m1, s_invvar, s_value;

    const int k   = blockIdx.x;
    const int tid = threadIdx.x;

    if (tid == 0) {
        const float p0 = params[k * 4 + 0];
        const float p1 = params[k * 4 + 1];
        const float p2 = params[k * 4 + 2];
        const float p3 = params[k * 4 + 3];

        // m = sigmoid(p) * (size - 1), fp32 exactly as the reference.
        s_m0 = __fmul_rn(sigmoid_ref(p0), (float)(OUT_NUM_ - 1));
        s_m1 = __fmul_rn(sigmoid_ref(p1), (float)(IN_NUM_ - 1));

        // sigma = (softplus(p2+2)+eps) * 50000 * 0.2 ; inv_var = 1/(eps+sigma)
        const float sp    = softplus_acc(__fadd_rn(p2, 2.0f));
        const float sigma = __fmul_rn(__fmul_rn(__fadd_rn(sp, EPS_),
                                                (float)OUT_NUM_), 0.2f);
        s_invvar = __fdiv_rn(1.0f, __fadd_rn(EPS_, sigma));
        s_value  = sigmoid_ref(p3);
    }
    __syncthreads();

    const float m0      = s_m0;
    const float m1      = s_m1;
    const float inv_var = s_invvar;

    if (tid < NPTS) {
        int i, j;
        if (tid < 4) {
            // FLOOR_MASK = product([T,F], repeat=2), True -> floor:
            // t0:(floor,floor) t1:(floor,ceil) t2:(ceil,floor) t3:(ceil,ceil)
            const float i_f = (tid & 2) ? ceilf(m0) : floorf(m0);
            const float j_f = (tid & 1) ? ceilf(m1) : floorf(m1);
            i = (int)i_f;
            j = (int)j_f;
        } else {
            const int s = (k * ADD_ + (tid - 4)) * 2;
            i = sampled[s + 0];
            j = sampled[s + 1];
        }

        const float di = (float)i - m0;
        const float dj = (float)j - m1;
        // props ~1 for neighbors, ~0 for sampled points; smooth quantity.
        const float arg  = -0.5f * (di * di + dj * dj) * inv_var;
        const float prop = (float)exp((double)arg);

        s_prop[tid] = prop;
        s_i[tid] = i;
        s_j[tid] = j;
    }
    __syncthreads();

    if (tid < NPTS) {
        float denom = 0.0f;
        #pragma unroll
        for (int t = 0; t < NPTS; t++)
            denom = __fadd_rn(denom, __fadd_rn(s_prop[t], EPS_));
        s_w[tid] = __fdiv_rn(__fmul_rn(s_value, s_prop[tid]), denom);
    }
    __syncthreads();

    // One warp per point: 32 lanes x float4 = 128 floats.
    const int warp = tid >> 5;
    const int lane = tid & 31;

    const float w = s_w[warp];
    const int   i = s_i[warp];
    const int   j = s_j[warp];

    const float4 v = __ldg((const float4*)(x + (size_t)j * FEAT_) + lane);
    const float a = v.x * w, b = v.y * w, c = v.z * w, d = v.w * w;

    float* dst = out + (size_t)i * FEAT_ + lane * 4;
    asm volatile("red.global.add.v4.f32 [%0], {%1,%2,%3,%4};"
                 :: "l"(dst), "f"(a), "f"(b), "f"(c), "f"(d)
                 : "memory");
}

extern "C" void kernel_launch(void* const* d_in, const int* in_sizes, int n_in,
                              void* d_out, int out_size) {
    const float* params  = (const float*)d_in[0];   // (K, 4)
    const float* x       = (const float*)d_in[1];   // (IN_NUM, 128)
    const int*   sampled = (const int*)  d_in[2];   // (K, 12, 2)
    float*       out     = (float*)d_out;           // (OUT_NUM, 128)

    // d_out is poisoned; we need zeros for the scatter-add.
    cudaMemsetAsync(out, 0, (size_t)out_size * sizeof(float));

    hyperlayer_scatter_kernel<<<K_NUM, 512>>>(params, x, sampled, out);
}

// round 11
// speedup vs baseline: 12.2250x; 12.2250x over previous
#include <cuda_runtime.h>
#include <cuda_bf16.h>
#include <cstdint>
#include <math.h>

// Problem constants (match reference)
#define K_NUM    131072
#define IN_NUM_  50000
#define OUT_NUM_ 50000
#define FEAT_    128
#define NPTS     16
#define ADD_     12
#define EPS_     1e-7f
#define MAX_SAMPLED (K_NUM * ADD_)

// ---------------------------------------------------------------------------
// Bit-exact sigmoid path (DO NOT TOUCH — verified rel_err 3.2e-7 in R10).
// Cephes-classic f32 exp as XLA:CPU emits on aarch64 NEON (FMA pmadd).
// ---------------------------------------------------------------------------
__device__ __forceinline__ float cephes_expf_fma(float x) {
    const float LOG2EF = 1.44269504088896341f;
    const float C1     = 0.693359375f;
    const float C2     = -2.12194440e-4f;

    float fx = __fmaf_rn(x, LOG2EF, 0.5f);
    fx = floorf(fx);

    const float tmp = __fmul_rn(fx, C1);
    const float z   = __fmul_rn(fx, C2);
    float xr = __fsub_rn(x, tmp);
    xr = __fsub_rn(xr, z);

    const float zz = __fmul_rn(xr, xr);

    float y =             1.9875691500e-4f;
    y = __fmaf_rn(y, xr,  1.3981999507e-3f);
    y = __fmaf_rn(y, xr,  8.3334519073e-3f);
    y = __fmaf_rn(y, xr,  4.1665795894e-2f);
    y = __fmaf_rn(y, xr,  1.6666665459e-1f);
    y = __fmaf_rn(y, xr,  5.0000001201e-1f);
    y = __fmaf_rn(y, zz,  xr);
    y = __fadd_rn(y, 1.0f);

    const int n = (int)fx;
    const float p2n = __int_as_float((n + 127) << 23);
    return __fmul_rn(y, p2n);
}

__device__ __forceinline__ float sigmoid_ref(float v) {
    const float e = cephes_expf_fma(-v);
    return __fdiv_rn(1.0f, __fadd_rn(1.0f, e));
}

__device__ __forceinline__ float softplus_acc(float v) {
    double d = (double)v;
    return (float)(fmax(d, 0.0) + log1p(exp(-fabs(d))));
}

// ---------------------------------------------------------------------------
// Scratch (static __device__ arrays — no allocation)
// ---------------------------------------------------------------------------
__device__ int4   g_nidx[K_NUM];        // (i0, i1, j0, j1) per edge
__device__ float4 g_nw[K_NUM];          // (w00, w01, w10, w11) per edge
__device__ int2   g_sij[MAX_SAMPLED];   // nonzero sampled (i, j)
__device__ float  g_sw[MAX_SAMPLED];    // nonzero sampled weight
__device__ int    g_scount;

// ---------------------------------------------------------------------------
// Kernel A: per-edge weight computation (1 thread / edge, no barriers)
// ---------------------------------------------------------------------------
__global__ void __launch_bounds__(256)
compute_weights_kernel(const float* __restrict__ params,
                       const int*   __restrict__ sampled)
{
    const int k = blockIdx.x * blockDim.x + threadIdx.x;
    if (k >= K_NUM) return;

    const float4 p = __ldg((const float4*)params + k);

    // Bit-exact reference math
    const float m0 = __fmul_rn(sigmoid_ref(p.x), (float)(OUT_NUM_ - 1));
    const float m1 = __fmul_rn(sigmoid_ref(p.y), (float)(IN_NUM_ - 1));
    const float sp    = softplus_acc(__fadd_rn(p.z, 2.0f));
    const float sigma = __fmul_rn(__fmul_rn(__fadd_rn(sp, EPS_),
                                            (float)OUT_NUM_), 0.2f);
    const float inv_var = __fdiv_rn(1.0f, __fadd_rn(EPS_, sigma));
    const float value   = sigmoid_ref(p.w);

    const float f0 = floorf(m0), c0 = ceilf(m0);
    const float f1 = floorf(m1), c1 = ceilf(m1);

    int   pi[NPTS], pj[NPTS];
    float prop[NPTS];

    // Neighbor order matches FLOOR_MASK: (T,T),(T,F),(F,T),(F,F), True->floor
    pi[0] = (int)f0; pj[0] = (int)f1;
    pi[1] = (int)f0; pj[1] = (int)c1;
    pi[2] = (int)c0; pj[2] = (int)f1;
    pi[3] = (int)c0; pj[3] = (int)c1;

    // Sampled: 24 ints = 6 x int4
    const int4* sp4 = (const int4*)(sampled + (size_t)k * (ADD_ * 2));
    #pragma unroll
    for (int q = 0; q < 6; q++) {
        const int4 v = __ldg(sp4 + q);
        pi[4 + q * 2]     = v.x;  pj[4 + q * 2]     = v.y;
        pi[4 + q * 2 + 1] = v.z;  pj[4 + q * 2 + 1] = v.w;
    }

    #pragma unroll
    for (int t = 0; t < NPTS; t++) {
        const float di = (float)pi[t] - m0;
        const float dj = (float)pj[t] - m1;
        const float arg = -0.5f * (di * di + dj * dj) * inv_var;
        // expf underflows to exactly 0 for arg < ~-103.97 -> skippable points
        prop[t] = (arg < -104.0f) ? 0.0f : expf(arg);
    }

    float denom = 0.0f;
    #pragma unroll
    for (int t = 0; t < NPTS; t++)
        denom = __fadd_rn(denom, __fadd_rn(prop[t], EPS_));
    const float scale = __fdiv_rn(value, denom);

    // Fused neighbor record: rows i0=floor0, i1=ceil0; cols j0=floor1, j1=ceil1
    g_nidx[k] = make_int4(pi[0], pi[2], pj[0], pj[1]);
    g_nw[k]   = make_float4(prop[0] * scale, prop[1] * scale,
                            prop[2] * scale, prop[3] * scale);

    // Compact nonzero sampled points (~0.4%)
    #pragma unroll
    for (int t = 4; t < NPTS; t++) {
        if (prop[t] != 0.0f) {
            const int pos = atomicAdd(&g_scount, 1);
            g_sij[pos] = make_int2(pi[t], pj[t]);
            g_sw[pos]  = prop[t] * scale;
        }
    }
}

// ---------------------------------------------------------------------------
// Kernel B: neighbor scatter (1 warp / edge): 2 gathers, 2 fused vector reds
// ---------------------------------------------------------------------------
__global__ void __launch_bounds__(256)
neighbor_scatter_kernel(const float* __restrict__ x,
                        float*       __restrict__ out)
{
    const int warp = (blockIdx.x * blockDim.x + threadIdx.x) >> 5;
    const int lane = threadIdx.x & 31;
    if (warp >= K_NUM) return;

    const int4   idx = g_nidx[warp];   // broadcast (same addr per warp)
    const float4 wv  = g_nw[warp];

    const float4 a = __ldg((const float4*)(x + (size_t)idx.z * FEAT_) + lane);
    const float4 b = __ldg((const float4*)(x + (size_t)idx.w * FEAT_) + lane);

    // Row i0: w00*x[j0] + w01*x[j1]
    {
        const float r0 = fmaf(wv.y, b.x, wv.x * a.x);
        const float r1 = fmaf(wv.y, b.y, wv.x * a.y);
        const float r2 = fmaf(wv.y, b.z, wv.x * a.z);
        const float r3 = fmaf(wv.y, b.w, wv.x * a.w);
        float* dst = out + (size_t)idx.x * FEAT_ + lane * 4;
        asm volatile("red.global.add.v4.f32 [%0], {%1,%2,%3,%4};"
                     :: "l"(dst), "f"(r0), "f"(r1), "f"(r2), "f"(r3)
                     : "memory");
    }
    // Row i1: w10*x[j0] + w11*x[j1]
    {
        const float r0 = fmaf(wv.w, b.x, wv.z * a.x);
        const float r1 = fmaf(wv.w, b.y, wv.z * a.y);
        const float r2 = fmaf(wv.w, b.z, wv.z * a.z);
        const float r3 = fmaf(wv.w, b.w, wv.z * a.w);
        float* dst = out + (size_t)idx.y * FEAT_ + lane * 4;
        asm volatile("red.global.add.v4.f32 [%0], {%1,%2,%3,%4};"
                     :: "l"(dst), "f"(r0), "f"(r1), "f"(r2), "f"(r3)
                     : "memory");
    }
}

// ---------------------------------------------------------------------------
// Kernel C: sampled scatter (grid-stride warps over compacted list)
// ---------------------------------------------------------------------------
__global__ void __launch_bounds__(256)
sampled_scatter_kernel(const float* __restrict__ x,
                       float*       __restrict__ out)
{
    const int warp   = (blockIdx.x * blockDim.x + threadIdx.x) >> 5;
    const int lane   = threadIdx.x & 31;
    const int nwarps = (gridDim.x * blockDim.x) >> 5;
    const int cnt    = g_scount;

    for (int e = warp; e < cnt; e += nwarps) {
        const int2  ij = g_sij[e];
        const float w  = g_sw[e];
        const float4 v = __ldg((const float4*)(x + (size_t)ij.y * FEAT_) + lane);
        float* dst = out + (size_t)ij.x * FEAT_ + lane * 4;
        asm volatile("red.global.add.v4.f32 [%0], {%1,%2,%3,%4};"
                     :: "l"(dst), "f"(v.x * w), "f"(v.y * w),
                        "f"(v.z * w), "f"(v.w * w)
                     : "memory");
    }
}

extern "C" void kernel_launch(void* const* d_in, const int* in_sizes, int n_in,
                              void* d_out, int out_size) {
    const float* params  = (const float*)d_in[0];   // (K, 4)
    const float* x       = (const float*)d_in[1];   // (IN_NUM, 128)
    const int*   sampled = (const int*)  d_in[2];   // (K, 12, 2)
    float*       out     = (float*)d_out;           // (OUT_NUM, 128)

    // Zero output and the sampled-list counter (both capturable memsets).
    cudaMemsetAsync(out, 0, (size_t)out_size * sizeof(float));
    void* cnt_addr = nullptr;
    cudaGetSymbolAddress(&cnt_addr, g_scount);
    cudaMemsetAsync(cnt_addr, 0, sizeof(int));

    compute_weights_kernel<<<(K_NUM + 255) / 256, 256>>>(params, sampled);
    neighbor_scatter_kernel<<<(K_NUM * 32) / 256, 256>>>(x, out);
    sampled_scatter_kernel<<<1024, 256>>>(x, out);
}

// round 12
// speedup vs baseline: 16.9939x; 1.3901x over previous
#include <cuda_runtime.h>
#include <cuda_bf16.h>
#include <cstdint>
#include <math.h>

// Problem constants (match reference)
#define K_NUM    131072
#define IN_NUM_  50000
#define OUT_NUM_ 50000
#define FEAT_    128
#define NPTS     16
#define ADD_     12
#define EPS_     1e-7f
#define MAX_SAMPLED (K_NUM * ADD_)

// Extra warps appended to the scatter kernel grid for the sampled list
#define SAMP_WARPS 8192

// ---------------------------------------------------------------------------
// Bit-exact sigmoid path (DO NOT TOUCH — verified rel_err 3.2e-7 in R10/R11).
// Cephes-classic f32 exp as XLA:CPU emits on aarch64 NEON (FMA pmadd).
// ---------------------------------------------------------------------------
__device__ __forceinline__ float cephes_expf_fma(float x) {
    const float LOG2EF = 1.44269504088896341f;
    const float C1     = 0.693359375f;
    const float C2     = -2.12194440e-4f;

    float fx = __fmaf_rn(x, LOG2EF, 0.5f);
    fx = floorf(fx);

    const float tmp = __fmul_rn(fx, C1);
    const float z   = __fmul_rn(fx, C2);
    float xr = __fsub_rn(x, tmp);
    xr = __fsub_rn(xr, z);

    const float zz = __fmul_rn(xr, xr);

    float y =             1.9875691500e-4f;
    y = __fmaf_rn(y, xr,  1.3981999507e-3f);
    y = __fmaf_rn(y, xr,  8.3334519073e-3f);
    y = __fmaf_rn(y, xr,  4.1665795894e-2f);
    y = __fmaf_rn(y, xr,  1.6666665459e-1f);
    y = __fmaf_rn(y, xr,  5.0000001201e-1f);
    y = __fmaf_rn(y, zz,  xr);
    y = __fadd_rn(y, 1.0f);

    const int n = (int)fx;
    const float p2n = __int_as_float((n + 127) << 23);
    return __fmul_rn(y, p2n);
}

__device__ __forceinline__ float sigmoid_ref(float v) {
    const float e = cephes_expf_fma(-v);
    return __fdiv_rn(1.0f, __fadd_rn(1.0f, e));
}

// fp32 softplus: max(x,0) + log1p(exp(-|x|)). Few-ulp accurate; sigma
// sensitivity analysis gives delta_prop/prop <= ~1e-5 << 1e-3 tolerance.
// (fp64 version cost ~19us/call-site in kernel A — removed in R12.)
__device__ __forceinline__ float softplus_f32(float v) {
    return fmaxf(v, 0.0f) + log1pf(expf(-fabsf(v)));
}

// ---------------------------------------------------------------------------
// Scratch (static __device__ arrays — no allocation)
// ---------------------------------------------------------------------------
__device__ int4   g_nidx[K_NUM];        // (i0, i1, j0, j1) per edge
__device__ float4 g_nw[K_NUM];          // (w00, w01, w10, w11) per edge
__device__ int2   g_sij[MAX_SAMPLED];   // nonzero sampled (i, j)
__device__ float  g_sw[MAX_SAMPLED];    // nonzero sampled weight
__device__ int    g_scount;

// ---------------------------------------------------------------------------
// Kernel A: per-edge weight computation (1 thread / edge, no barriers)
// ---------------------------------------------------------------------------
__global__ void __launch_bounds__(256)
compute_weights_kernel(const float* __restrict__ params,
                       const int*   __restrict__ sampled)
{
    const int k = blockIdx.x * blockDim.x + threadIdx.x;
    if (k >= K_NUM) return;

    const float4 p = __ldg((const float4*)params + k);

    // Bit-exact reference math (sigmoids); fp32 softplus (insensitive).
    const float m0 = __fmul_rn(sigmoid_ref(p.x), (float)(OUT_NUM_ - 1));
    const float m1 = __fmul_rn(sigmoid_ref(p.y), (float)(IN_NUM_ - 1));
    const float sp    = softplus_f32(__fadd_rn(p.z, 2.0f));
    const float sigma = __fmul_rn(__fmul_rn(__fadd_rn(sp, EPS_),
                                            (float)OUT_NUM_), 0.2f);
    const float inv_var = __fdiv_rn(1.0f, __fadd_rn(EPS_, sigma));
    const float value   = sigmoid_ref(p.w);

    const float f0 = floorf(m0), c0 = ceilf(m0);
    const float f1 = floorf(m1), c1 = ceilf(m1);

    int   pi[NPTS], pj[NPTS];
    float prop[NPTS];

    // Neighbor order matches FLOOR_MASK: (T,T),(T,F),(F,T),(F,F), True->floor
    pi[0] = (int)f0; pj[0] = (int)f1;
    pi[1] = (int)f0; pj[1] = (int)c1;
    pi[2] = (int)c0; pj[2] = (int)f1;
    pi[3] = (int)c0; pj[3] = (int)c1;

    // Sampled: 24 ints = 6 x int4
    const int4* sp4 = (const int4*)(sampled + (size_t)k * (ADD_ * 2));
    #pragma unroll
    for (int q = 0; q < 6; q++) {
        const int4 v = __ldg(sp4 + q);
        pi[4 + q * 2]     = v.x;  pj[4 + q * 2]     = v.y;
        pi[4 + q * 2 + 1] = v.z;  pj[4 + q * 2 + 1] = v.w;
    }

    #pragma unroll
    for (int t = 0; t < NPTS; t++) {
        const float di = (float)pi[t] - m0;
        const float dj = (float)pj[t] - m1;
        const float arg = -0.5f * (di * di + dj * dj) * inv_var;
        // expf underflows to exactly 0 below ~-103.97 -> skippable points
        prop[t] = (arg < -104.0f) ? 0.0f : expf(arg);
    }

    float denom = 0.0f;
    #pragma unroll
    for (int t = 0; t < NPTS; t++)
        denom = __fadd_rn(denom, __fadd_rn(prop[t], EPS_));
    const float scale = __fdiv_rn(value, denom);

    // Fused neighbor record: rows i0=floor0, i1=ceil0; cols j0=floor1, j1=ceil1
    g_nidx[k] = make_int4(pi[0], pi[2], pj[0], pj[1]);
    g_nw[k]   = make_float4(prop[0] * scale, prop[1] * scale,
                            prop[2] * scale, prop[3] * scale);

    // Compact nonzero sampled points (~0.4%)
    #pragma unroll
    for (int t = 4; t < NPTS; t++) {
        if (prop[t] != 0.0f) {
            const int pos = atomicAdd(&g_scount, 1);
            g_sij[pos] = make_int2(pi[t], pj[t]);
            g_sw[pos]  = prop[t] * scale;
        }
    }
}

// ---------------------------------------------------------------------------
// Kernel B: fused scatter. Warps < K_NUM: neighbor work (2 gathers, 2 fused
// vector reds). Warps >= K_NUM: grid-stride over the compacted sampled list.
// ---------------------------------------------------------------------------
__global__ void __launch_bounds__(256)
scatter_kernel(const float* __restrict__ x,
               float*       __restrict__ out)
{
    const int warp = (blockIdx.x * blockDim.x + threadIdx.x) >> 5;
    const int lane = threadIdx.x & 31;

    if (warp < K_NUM) {
        const int4   idx = g_nidx[warp];   // broadcast (same addr per warp)
        const float4 wv  = g_nw[warp];

        const float4 a = __ldg((const float4*)(x + (size_t)idx.z * FEAT_) + lane);
        const float4 b = __ldg((const float4*)(x + (size_t)idx.w * FEAT_) + lane);

        // Row i0: w00*x[j0] + w01*x[j1]
        {
            const float r0 = fmaf(wv.y, b.x, wv.x * a.x);
            const float r1 = fmaf(wv.y, b.y, wv.x * a.y);
            const float r2 = fmaf(wv.y, b.z, wv.x * a.z);
            const float r3 = fmaf(wv.y, b.w, wv.x * a.w);
            float* dst = out + (size_t)idx.x * FEAT_ + lane * 4;
            asm volatile("red.global.add.v4.f32 [%0], {%1,%2,%3,%4};"
                         :: "l"(dst), "f"(r0), "f"(r1), "f"(r2), "f"(r3)
                         : "memory");
        }
        // Row i1: w10*x[j0] + w11*x[j1]
        {
            const float r0 = fmaf(wv.w, b.x, wv.z * a.x);
            const float r1 = fmaf(wv.w, b.y, wv.z * a.y);
            const float r2 = fmaf(wv.w, b.z, wv.z * a.z);
            const float r3 = fmaf(wv.w, b.w, wv.z * a.w);
            float* dst = out + (size_t)idx.y * FEAT_ + lane * 4;
            asm volatile("red.global.add.v4.f32 [%0], {%1,%2,%3,%4};"
                         :: "l"(dst), "f"(r0), "f"(r1), "f"(r2), "f"(r3)
                         : "memory");
        }
    } else {
        const int sw  = warp - K_NUM;       // 0 .. SAMP_WARPS-1
        const int cnt = g_scount;
        for (int e = sw; e < cnt; e += SAMP_WARPS) {
            const int2  ij = g_sij[e];
            const float w  = g_sw[e];
            const float4 v = __ldg((const float4*)(x + (size_t)ij.y * FEAT_) + lane);
            float* dst = out + (size_t)ij.x * FEAT_ + lane * 4;
            asm volatile("red.global.add.v4.f32 [%0], {%1,%2,%3,%4};"
                         :: "l"(dst), "f"(v.x * w), "f"(v.y * w),
                            "f"(v.z * w), "f"(v.w * w)
                         : "memory");
        }
    }
}

extern "C" void kernel_launch(void* const* d_in, const int* in_sizes, int n_in,
                              void* d_out, int out_size) {
    const float* params  = (const float*)d_in[0];   // (K, 4)
    const float* x       = (const float*)d_in[1];   // (IN_NUM, 128)
    const int*   sampled = (const int*)  d_in[2];   // (K, 12, 2)
    float*       out     = (float*)d_out;           // (OUT_NUM, 128)

    // Zero output and the sampled-list counter (both capturable memsets).
    cudaMemsetAsync(out, 0, (size_t)out_size * sizeof(float));
    void* cnt_addr = nullptr;
    cudaGetSymbolAddress(&cnt_addr, g_scount);
    cudaMemsetAsync(cnt_addr, 0, sizeof(int));

    compute_weights_kernel<<<(K_NUM + 255) / 256, 256>>>(params, sampled);

    const int total_warps = K_NUM + SAMP_WARPS;
    scatter_kernel<<<(total_warps * 32) / 256, 256>>>(x, out);
}

// round 13
// speedup vs baseline: 19.7703x; 1.1634x over previous
#include <cuda_runtime.h>
#include <cuda_bf16.h>
#include <cstdint>
#include <math.h>

// Problem constants (match reference)
#define K_NUM    131072
#define IN_NUM_  50000
#define OUT_NUM_ 50000
#define FEAT_    128
#define NPTS     16
#define ADD_     12
#define EPS_     1e-7f

// Per-output-row bucket capacity. Neighbor hits/row ~ Poisson(<=8.4) at the
// density peak -> P(>=40) ~ 1e-25; overflow list guards correctness anyway.
#define CAP      40
#define OVF_CAP  65536

// ---------------------------------------------------------------------------
// Bit-exact sigmoid path (DO NOT TOUCH — verified rel_err 3.2e-7 in R10-R12).
// Cephes-classic f32 exp as XLA:CPU emits on aarch64 NEON (FMA pmadd).
// ---------------------------------------------------------------------------
__device__ __forceinline__ float cephes_expf_fma(float x) {
    const float LOG2EF = 1.44269504088896341f;
    const float C1     = 0.693359375f;
    const float C2     = -2.12194440e-4f;

    float fx = __fmaf_rn(x, LOG2EF, 0.5f);
    fx = floorf(fx);

    const float tmp = __fmul_rn(fx, C1);
    const float z   = __fmul_rn(fx, C2);
    float xr = __fsub_rn(x, tmp);
    xr = __fsub_rn(xr, z);

    const float zz = __fmul_rn(xr, xr);

    float y =             1.9875691500e-4f;
    y = __fmaf_rn(y, xr,  1.3981999507e-3f);
    y = __fmaf_rn(y, xr,  8.3334519073e-3f);
    y = __fmaf_rn(y, xr,  4.1665795894e-2f);
    y = __fmaf_rn(y, xr,  1.6666665459e-1f);
    y = __fmaf_rn(y, xr,  5.0000001201e-1f);
    y = __fmaf_rn(y, zz,  xr);
    y = __fadd_rn(y, 1.0f);

    const int n = (int)fx;
    const float p2n = __int_as_float((n + 127) << 23);
    return __fmul_rn(y, p2n);
}

__device__ __forceinline__ float sigmoid_ref(float v) {
    const float e = cephes_expf_fma(-v);
    return __fdiv_rn(1.0f, __fadd_rn(1.0f, e));
}

// fp32 softplus (sigma sensitivity ~1e-5 << 1e-3 tolerance; verified R12).
__device__ __forceinline__ float softplus_f32(float v) {
    return fmaxf(v, 0.0f) + log1pf(expf(-fabsf(v)));
}

// ---------------------------------------------------------------------------
// Scratch (static __device__ arrays — no allocation)
// Record format: float4( as_float(j0), as_float(j1), w0, w1 )
//   contribution to its row: w0*x[j0] + w1*x[j1]   (w1==0 -> skip 2nd gather)
// ---------------------------------------------------------------------------
__device__ int    g_cnt[OUT_NUM_];
__device__ float4 g_entry[(size_t)OUT_NUM_ * CAP];   // 25.6 MB
__device__ int    g_ovf_cnt;
__device__ float4 g_ovf[OVF_CAP];                    // (as_float(i), as_float(j), w, 0)

__device__ __forceinline__ void push_entry(int row, int j0, int j1,
                                           float w0, float w1) {
    const int pos = atomicAdd(&g_cnt[row], 1);
    if (pos < CAP) {
        g_entry[(size_t)row * CAP + pos] =
            make_float4(__int_as_float(j0), __int_as_float(j1), w0, w1);
    } else {
        int op = atomicAdd(&g_ovf_cnt, 1);
        if (op < OVF_CAP)
            g_ovf[op] = make_float4(__int_as_float(row), __int_as_float(j0), w0, 0.0f);
        if (w1 != 0.0f) {
            op = atomicAdd(&g_ovf_cnt, 1);
            if (op < OVF_CAP)
                g_ovf[op] = make_float4(__int_as_float(row), __int_as_float(j1), w1, 0.0f);
        }
    }
}

// ---------------------------------------------------------------------------
// Kernel A: per-edge weight computation + bucket append (1 thread / edge)
// ---------------------------------------------------------------------------
__global__ void __launch_bounds__(256)
compute_weights_kernel(const float* __restrict__ params,
                       const int*   __restrict__ sampled)
{
    const int k = blockIdx.x * blockDim.x + threadIdx.x;
    if (k >= K_NUM) return;

    const float4 p = __ldg((const float4*)params + k);

    // Bit-exact reference math (sigmoids); fp32 softplus (insensitive).
    const float m0 = __fmul_rn(sigmoid_ref(p.x), (float)(OUT_NUM_ - 1));
    const float m1 = __fmul_rn(sigmoid_ref(p.y), (float)(IN_NUM_ - 1));
    const float sp    = softplus_f32(__fadd_rn(p.z, 2.0f));
    const float sigma = __fmul_rn(__fmul_rn(__fadd_rn(sp, EPS_),
                                            (float)OUT_NUM_), 0.2f);
    const float inv_var = __fdiv_rn(1.0f, __fadd_rn(EPS_, sigma));
    const float value   = sigmoid_ref(p.w);

    const float f0 = floorf(m0), c0 = ceilf(m0);
    const float f1 = floorf(m1), c1 = ceilf(m1);

    int   pi[NPTS], pj[NPTS];
    float prop[NPTS];

    // Neighbor order matches FLOOR_MASK: (T,T),(T,F),(F,T),(F,F), True->floor
    pi[0] = (int)f0; pj[0] = (int)f1;
    pi[1] = (int)f0; pj[1] = (int)c1;
    pi[2] = (int)c0; pj[2] = (int)f1;
    pi[3] = (int)c0; pj[3] = (int)c1;

    const int4* sp4 = (const int4*)(sampled + (size_t)k * (ADD_ * 2));
    #pragma unroll
    for (int q = 0; q < 6; q++) {
        const int4 v = __ldg(sp4 + q);
        pi[4 + q * 2]     = v.x;  pj[4 + q * 2]     = v.y;
        pi[4 + q * 2 + 1] = v.z;  pj[4 + q * 2 + 1] = v.w;
    }

    #pragma unroll
    for (int t = 0; t < NPTS; t++) {
        const float di = (float)pi[t] - m0;
        const float dj = (float)pj[t] - m1;
        const float arg = -0.5f * (di * di + dj * dj) * inv_var;
        // expf underflows to exactly 0 below ~-103.97 -> skippable points
        prop[t] = (arg < -104.0f) ? 0.0f : expf(arg);
    }

    float denom = 0.0f;
    #pragma unroll
    for (int t = 0; t < NPTS; t++)
        denom = __fadd_rn(denom, __fadd_rn(prop[t], EPS_));
    const float scale = __fdiv_rn(value, denom);

    // Fused neighbor records: row i0 gets (w00,w01), row i1 gets (w10,w11)
    const int i0 = pi[0], i1 = pi[2], j0 = pj[0], j1 = pj[1];
    push_entry(i0, j0, j1, prop[0] * scale, prop[1] * scale);
    push_entry(i1, j0, j1, prop[2] * scale, prop[3] * scale);

    // Nonzero sampled points (~0.4%): single-input records (w1 = 0)
    #pragma unroll
    for (int t = 4; t < NPTS; t++) {
        if (prop[t] != 0.0f)
            push_entry(pi[t], pj[t], pj[t], prop[t] * scale, 0.0f);
    }
}

// ---------------------------------------------------------------------------
// Kernel B: one warp per output row — gather bucket, accumulate in registers,
// single plain STG per row. No atomics, no output memset needed.
// ---------------------------------------------------------------------------
__global__ void __launch_bounds__(256)
row_scatter_kernel(const float* __restrict__ x,
                   float*       __restrict__ out)
{
    const int row  = (blockIdx.x * blockDim.x + threadIdx.x) >> 5;
    const int lane = threadIdx.x & 31;
    if (row >= OUT_NUM_) return;

    const int n = min(g_cnt[row], CAP);
    const float4* base = g_entry + (size_t)row * CAP;

    float ax = 0.0f, ay = 0.0f, az = 0.0f, aw = 0.0f;

    if (n > 0) {
        float4 rec = base[0];                       // warp-broadcast load
        for (int e = 0; e < n; e++) {
            const float4 nxt = (e + 1 < n) ? base[e + 1] : rec;  // prefetch
            const int j0 = __float_as_int(rec.x);
            const float4 a = __ldg((const float4*)(x + (size_t)j0 * FEAT_) + lane);
            ax = fmaf(rec.z, a.x, ax);
            ay = fmaf(rec.z, a.y, ay);
            az = fmaf(rec.z, a.z, az);
            aw = fmaf(rec.z, a.w, aw);
            if (rec.w != 0.0f) {                    // warp-uniform branch
                const int j1 = __float_as_int(rec.y);
                const float4 b = __ldg((const float4*)(x + (size_t)j1 * FEAT_) + lane);
                ax = fmaf(rec.w, b.x, ax);
                ay = fmaf(rec.w, b.y, ay);
                az = fmaf(rec.w, b.z, az);
                aw = fmaf(rec.w, b.w, aw);
            }
            rec = nxt;
        }
    }

    ((float4*)(out + (size_t)row * FEAT_))[lane] = make_float4(ax, ay, az, aw);
}

// ---------------------------------------------------------------------------
// Kernel C: overflow entries (normally zero) — atomic red after the STG pass.
// Stream-ordered after kernel B, so no ST/RED race.
// ---------------------------------------------------------------------------
__global__ void __launch_bounds__(256)
overflow_kernel(const float* __restrict__ x,
                float*       __restrict__ out)
{
    const int warp   = (blockIdx.x * blockDim.x + threadIdx.x) >> 5;
    const int lane   = threadIdx.x & 31;
    const int nwarps = (gridDim.x * blockDim.x) >> 5;
    const int cnt    = min(g_ovf_cnt, OVF_CAP);

    for (int e = warp; e < cnt; e += nwarps) {
        const float4 rec = g_ovf[e];
        const int i = __float_as_int(rec.x);
        const int j = __float_as_int(rec.y);
        const float w = rec.z;
        const float4 v = __ldg((const float4*)(x + (size_t)j * FEAT_) + lane);
        float* dst = out + (size_t)i * FEAT_ + lane * 4;
        asm volatile("red.global.add.v4.f32 [%0], {%1,%2,%3,%4};"
                     :: "l"(dst), "f"(v.x * w), "f"(v.y * w),
                        "f"(v.z * w), "f"(v.w * w)
                     : "memory");
    }
}

extern "C" void kernel_launch(void* const* d_in, const int* in_sizes, int n_in,
                              void* d_out, int out_size) {
    const float* params  = (const float*)d_in[0];   // (K, 4)
    const float* x       = (const float*)d_in[1];   // (IN_NUM, 128)
    const int*   sampled = (const int*)  d_in[2];   // (K, 12, 2)
    float*       out     = (float*)d_out;           // (OUT_NUM, 128)

    // Zero bucket counters + overflow counter (no output memset needed).
    void* cnt_addr = nullptr;
    cudaGetSymbolAddress(&cnt_addr, g_cnt);
    cudaMemsetAsync(cnt_addr, 0, OUT_NUM_ * sizeof(int));
    void* ovf_addr = nullptr;
    cudaGetSymbolAddress(&ovf_addr, g_ovf_cnt);
    cudaMemsetAsync(ovf_addr, 0, sizeof(int));

    compute_weights_kernel<<<(K_NUM + 255) / 256, 256>>>(params, sampled);
    row_scatter_kernel<<<(OUT_NUM_ * 32 + 255) / 256, 256>>>(x, out);
    overflow_kernel<<<16, 256>>>(x, out);
}